// round 13
// baseline (speedup 1.0000x reference)
#include <cuda_runtime.h>
#include <math.h>

#define N_NODES 8192
#define N_EDGES 4096
#define NNZ_IN  65536
#define DIN_    256
#define D_      128

#define EM1     1.7182818284590452f
#define INV_TEMP (1.0f/11.313708498984761f)  // 1/sqrt(128)

typedef unsigned long long ull;

// ---------------- scratch ----------------
__device__ unsigned int g_bitmap[(size_t)N_NODES * N_EDGES / 32];  // 4 MB
__device__ int   g_kept_n[NNZ_IN];
__device__ int   g_kept_e[NNZ_IN];
__device__ int   g_kept_count;
__device__ int   g_deg_e[N_EDGES];
__device__ int   g_deg_n[N_NODES];
__device__ int   g_rowptr_e[N_EDGES + 1];
__device__ int   g_rowptr_n[N_NODES + 1];
__device__ int   g_cur_e[N_EDGES];
__device__ int   g_cur_n[N_NODES];
__device__ int   g_csr_e[NNZ_IN];
__device__ int   g_csr_n[NNZ_IN];
__device__ float g_x4[(size_t)N_NODES * D_];
__device__ float g_xt[(size_t)N_NODES * D_];
__device__ float g_rowv[N_NODES];
__device__ float g_edge4[(size_t)N_EDGES * D_];
__device__ float g_Y[(size_t)N_EDGES * D_];
__device__ float g_Y2[(size_t)N_EDGES * D_];
__device__ float g_Pval[NNZ_IN];
__device__ float g_Qval[NNZ_IN];
__device__ float g_score[NNZ_IN];
__device__ float g_v[N_NODES];
__device__ float g_w[N_NODES];
__device__ float g_r[N_NODES];
__device__ float g_s[D_], g_cxt[D_], g_t[D_], g_p1[D_], g_p2[D_];
__device__ float g_alpha;

// ---------------- helpers ----------------
__device__ __forceinline__ void ffma2(ull &acc, ull a, ull b) {
    asm("fma.rn.f32x2 %0, %1, %2, %0;" : "+l"(acc) : "l"(a), "l"(b));
}
__device__ __forceinline__ ull pack2(float v) {
    ull r;
    asm("mov.b64 %0, {%1, %1};" : "=l"(r) : "f"(v));
    return r;
}
__device__ __forceinline__ void unpack2(ull a, float &lo, float &hi) {
    asm("mov.b64 {%0, %1}, %2;" : "=f"(lo), "=f"(hi) : "l"(a));
}
__device__ __forceinline__ void fma4(float4 &a, float p, const float4 &v) {
    a.x = fmaf(p, v.x, a.x); a.y = fmaf(p, v.y, a.y);
    a.z = fmaf(p, v.z, a.z); a.w = fmaf(p, v.w, a.w);
}

// ---------------- kernels ----------------

__global__ void k_zero_small() {
    int i = threadIdx.x;
    if (i < D_) { g_s[i]=0.f; g_cxt[i]=0.f; g_t[i]=0.f; g_p1[i]=0.f; g_p2[i]=0.f; }
    if (i == 0) g_alpha = 0.f;
}

__global__ void k_zero_big() {
    int i = blockIdx.x * blockDim.x + threadIdx.x;
    int stride = gridDim.x * blockDim.x;
    uint4 z4 = make_uint4(0,0,0,0);
    uint4* bm = (uint4*)g_bitmap;
    for (int j = i; j < (int)(sizeof(g_bitmap)/16); j += stride) bm[j] = z4;
    for (int j = i; j < N_EDGES; j += stride) { g_deg_e[j] = 0; g_cur_e[j] = 0; }
    for (int j = i; j < N_NODES; j += stride) { g_deg_n[j] = 0; g_cur_n[j] = 0; g_v[j] = 0.f; }
    if (i == 0) g_kept_count = 0;
}

__global__ void k_dedup(const int* __restrict__ nodes, const int* __restrict__ edges) {
    int i = blockIdx.x * blockDim.x + threadIdx.x;
    if (i >= NNZ_IN) return;
    int n = __ldg(&nodes[i]), e = __ldg(&edges[i]);
    size_t bit = (size_t)e * N_NODES + (size_t)n;
    unsigned int mask = 1u << (bit & 31);
    unsigned int old = atomicOr(&g_bitmap[bit >> 5], mask);
    if (!(old & mask)) {
        int k = atomicAdd(&g_kept_count, 1);
        g_kept_n[k] = n; g_kept_e[k] = e;
        atomicAdd(&g_deg_e[e], 1);
        atomicAdd(&g_deg_n[n], 1);
    }
}

// scans; node pass also emits w,r
__global__ void k_scan2() {
    int which = blockIdx.x;
    const int* cnt = which ? g_deg_n : g_deg_e;
    int* rp        = which ? g_rowptr_n : g_rowptr_e;
    int L          = which ? N_NODES : N_EDGES;
    int tid = threadIdx.x, lane = tid & 31, wid = tid >> 5;
    int C = L >> 10;
    int base = tid * C;
    int loc[8];
    int s = 0;
    for (int j = 0; j < C; j++) { loc[j] = cnt[base + j]; s += loc[j]; }
    int ss = s;
#pragma unroll
    for (int o = 1; o < 32; o <<= 1) { int v = __shfl_up_sync(0xffffffffu, ss, o); if (lane >= o) ss += v; }
    __shared__ int wsum[32];
    if (lane == 31) wsum[wid] = ss;
    __syncthreads();
    if (wid == 0) {
        int v = wsum[lane];
#pragma unroll
        for (int o = 1; o < 32; o <<= 1) { int u = __shfl_up_sync(0xffffffffu, v, o); if (lane >= o) v += u; }
        wsum[lane] = v;
    }
    __syncthreads();
    int run = ss - s + (wid ? wsum[wid - 1] : 0);
    for (int j = 0; j < C; j++) { rp[base + j] = run; run += loc[j]; }
    if (tid == 1023) rp[L] = run;
    if (which) {
        for (int j = 0; j < C; j++) {
            int dn = loc[j];
            float g = 1.0f / ((float)N_EDGES + (float)dn * EM1);
            g_w[base + j] = g + (dn == 0 ? (1.0f / N_EDGES) : 0.0f);
            g_r[base + j] = (dn > 0) ? ((float)dn * EM1 * g + 1.0f) : 0.0f;
        }
    }
}

__global__ void k_fill() {
    int i = blockIdx.x * blockDim.x + threadIdx.x;
    int kc = g_kept_count;
    if (i < NNZ_IN) {
        if (i >= kc) return;
        int e = g_kept_e[i];
        int pe = g_rowptr_e[e] + atomicAdd(&g_cur_e[e], 1);
        g_csr_e[pe] = i;
    } else {
        i -= NNZ_IN;
        if (i >= kc) return;
        int n = g_kept_n[i];
        int pn = g_rowptr_n[n] + atomicAdd(&g_cur_n[n], 1);
        g_csr_n[pn] = i;
    }
}

// x4 = x@W2 ; xt = x@W + b ; fused rowv + colsums.
// 256 threads: 4 row-groups of 8 rows; each thread owns a COLUMN PAIR (d0, d0+1).
// Per kk: 2 LDG.64 + 2 LDS.128 (shared across both cols) + 16 FFMA2.
__global__ void __launch_bounds__(256, 3) k_gemm_x(const float* __restrict__ x,
                                                   const float* __restrict__ W,
                                                   const float* __restrict__ W2,
                                                   const float* __restrict__ bias,
                                                   const float* __restrict__ q_ctx) {
    const int ROWS = 32, KC = 32, HR = 8, STRIDE = 36;
    __shared__ __align__(16) float xs[2][KC * STRIDE];
    __shared__ float rvs[ROWS];
    int tid  = threadIdx.x;
    int grp  = tid >> 6;            // 0..3
    int d0   = (tid & 63) * 2;      // column pair base
    int r0   = blockIdx.x * ROWS;
    int rbase = grp * HR;
    // a[c][r]: column c of pair, row-pair r (f32x2 packs rows 2r,2r+1)
    ull a1[2][4], a2[2][4];
#pragma unroll
    for (int c = 0; c < 2; c++)
#pragma unroll
        for (int r = 0; r < 4; r++) { a1[c][r] = 0ull; a2[c][r] = 0ull; }

#pragma unroll
    for (int t = tid; t < ROWS * KC; t += 256) {
        int rr = t >> 5, cc = t & 31;
        xs[0][cc * STRIDE + rr] = x[(size_t)(r0 + rr) * DIN_ + cc];
    }
    __syncthreads();

    const int NT = DIN_ / KC;  // 8
    for (int kt = 0; kt < NT; kt++) {
        int cur = kt & 1;
        float pf[4];
        if (kt + 1 < NT) {
            int k0n = (kt + 1) * KC;
#pragma unroll
            for (int t = 0; t < 4; t++) {
                int idx = tid + t * 256;
                int rr = idx >> 5, cc = idx & 31;
                pf[t] = x[(size_t)(r0 + rr) * DIN_ + k0n + cc];
            }
        }
        int k0 = kt * KC;
#pragma unroll
        for (int kk = 0; kk < KC; kk++) {
            float2 wv  = *(const float2*)&W [(size_t)(k0 + kk) * D_ + d0];
            float2 w2v = *(const float2*)&W2[(size_t)(k0 + kk) * D_ + d0];
            ull wp0  = pack2(wv.x),  wp1  = pack2(wv.y);
            ull w2p0 = pack2(w2v.x), w2p1 = pack2(w2v.y);
            const ulonglong2* xp = (const ulonglong2*)&xs[cur][kk * STRIDE + rbase];
            ulonglong2 xv0 = xp[0];
            ulonglong2 xv1 = xp[1];
            ffma2(a1[0][0], xv0.x, wp0);  ffma2(a1[0][1], xv0.y, wp0);
            ffma2(a1[0][2], xv1.x, wp0);  ffma2(a1[0][3], xv1.y, wp0);
            ffma2(a1[1][0], xv0.x, wp1);  ffma2(a1[1][1], xv0.y, wp1);
            ffma2(a1[1][2], xv1.x, wp1);  ffma2(a1[1][3], xv1.y, wp1);
            ffma2(a2[0][0], xv0.x, w2p0); ffma2(a2[0][1], xv0.y, w2p0);
            ffma2(a2[0][2], xv1.x, w2p0); ffma2(a2[0][3], xv1.y, w2p0);
            ffma2(a2[1][0], xv0.x, w2p1); ffma2(a2[1][1], xv0.y, w2p1);
            ffma2(a2[1][2], xv1.x, w2p1); ffma2(a2[1][3], xv1.y, w2p1);
        }
        if (kt + 1 < NT) {
            __syncthreads();
#pragma unroll
            for (int t = 0; t < 4; t++) {
                int idx = tid + t * 256;
                int rr = idx >> 5, cc = idx & 31;
                xs[cur ^ 1][cc * STRIDE + rr] = pf[t];
            }
            __syncthreads();
        }
    }

    if (tid < ROWS) rvs[tid] = 0.f;
    __syncthreads();

    float2 bv = *(const float2*)&bias[d0];
    float2 qv = *(const float2*)&q_ctx[d0];
    float ct0 = 0.f, ct1 = 0.f, c40 = 0.f, c41 = 0.f;
    int lane = tid & 31;
#pragma unroll
    for (int r = 0; r < 4; r++) {
        int row = r0 + rbase + 2*r;
        float tA0, tA1, tB0, tB1;       // xt: col0 rows(lo,hi), col1 rows(lo,hi)
        float fA0, fA1, fB0, fB1;       // x4
        unpack2(a1[0][r], tA0, tA1);
        unpack2(a1[1][r], tB0, tB1);
        unpack2(a2[0][r], fA0, fA1);
        unpack2(a2[1][r], fB0, fB1);
        tA0 += bv.x; tA1 += bv.x; tB0 += bv.y; tB1 += bv.y;
        *(float2*)&g_xt[(size_t)(row    ) * D_ + d0] = make_float2(tA0, tB0);
        *(float2*)&g_xt[(size_t)(row + 1) * D_ + d0] = make_float2(tA1, tB1);
        *(float2*)&g_x4[(size_t)(row    ) * D_ + d0] = make_float2(fA0, fB0);
        *(float2*)&g_x4[(size_t)(row + 1) * D_ + d0] = make_float2(fA1, fB1);
        ct0 += tA0 + tA1; ct1 += tB0 + tB1;
        c40 += fA0 + fA1; c41 += fB0 + fB1;
        // rowv partials: row even = fA0*q0 + fB0*q1 ; row odd = fA1*q0 + fB1*q1
        float p0 = fA0 * qv.x + fB0 * qv.y;
        float p1 = fA1 * qv.x + fB1 * qv.y;
#pragma unroll
        for (int o = 16; o; o >>= 1) {
            p0 += __shfl_xor_sync(0xffffffffu, p0, o);
            p1 += __shfl_xor_sync(0xffffffffu, p1, o);
        }
        if (lane == 0) {
            atomicAdd(&rvs[rbase + 2*r],     p0);
            atomicAdd(&rvs[rbase + 2*r + 1], p1);
        }
    }
    atomicAdd(&g_s[d0],       c40);
    atomicAdd(&g_s[d0 + 1],   c41);
    atomicAdd(&g_cxt[d0],     ct0);
    atomicAdd(&g_cxt[d0 + 1], ct1);
    __syncthreads();
    if (tid < ROWS) g_rowv[r0 + tid] = rvs[tid] * INV_TEMP;
}

// per edge (warp per edge) + fused edge4 = edge @ W3. (round-11 proven)
__global__ void __launch_bounds__(256) k_edge(const float* __restrict__ W3) {
    __shared__ __align__(16) float se[8][132];
    int tid = threadIdx.x, lane = tid & 31, wid = tid >> 5;
    int e = blockIdx.x * 8 + wid;
    int beg = g_rowptr_e[e], end = g_rowptr_e[e + 1];
    int deg = end - beg;
    float c = 1.0f / ((float)N_NODES + (float)deg * EM1);
    float u = c + (deg == 0 ? (1.0f / N_NODES) : 0.0f);

    float4 at = make_float4(0.f,0.f,0.f,0.f);
    float4 ay = make_float4(0.f,0.f,0.f,0.f);

    if (deg <= 32) {
        int k = 0, n = 0; float rv = -INFINITY;
        if (lane < deg) {
            k = g_csr_e[beg + lane];
            n = g_kept_n[k];
            rv = g_rowv[n];
        }
        float m = rv;
#pragma unroll
        for (int o = 16; o; o >>= 1) m = fmaxf(m, __shfl_xor_sync(0xffffffffu, m, o));
        float ez = (lane < deg) ? expf(rv - m) : 0.f;
        float z = ez;
#pragma unroll
        for (int o = 16; o; o >>= 1) z += __shfl_xor_sync(0xffffffffu, z, o);
        float invz = (deg > 0) ? (1.0f / z) : 0.f;
        float p = EM1 * c + ez * invz;
        if (lane < deg) {
            g_Pval[k] = p;
            atomicAdd(&g_v[n], u * p);
        }
        for (int t = 0; t < deg; t++) {
            int   nn = __shfl_sync(0xffffffffu, n, t);
            float pp = __shfl_sync(0xffffffffu, p, t);
            size_t roff = (size_t)nn * D_;
            float4 vt = ((const float4*)&g_xt[roff])[lane];
            float4 vy = ((const float4*)&g_x4[roff])[lane];
            fma4(at, pp, vt);
            fma4(ay, pp, vy);
        }
    } else {
        float m = -INFINITY;
        for (int j = lane; j < deg; j += 32)
            m = fmaxf(m, g_rowv[g_kept_n[g_csr_e[beg + j]]]);
#pragma unroll
        for (int o = 16; o; o >>= 1) m = fmaxf(m, __shfl_xor_sync(0xffffffffu, m, o));
        float z = 0.f;
        for (int j = lane; j < deg; j += 32)
            z += expf(g_rowv[g_kept_n[g_csr_e[beg + j]]] - m);
#pragma unroll
        for (int o = 16; o; o >>= 1) z += __shfl_xor_sync(0xffffffffu, z, o);
        float invz = 1.0f / z;
        for (int j0 = 0; j0 < deg; j0 += 32) {
            int jj = j0 + lane;
            int n = 0; float p = 0.f;
            if (jj < deg) {
                int k = g_csr_e[beg + jj];
                n = g_kept_n[k];
                p = EM1 * c + expf(g_rowv[n] - m) * invz;
                g_Pval[k] = p;
                atomicAdd(&g_v[n], u * p);
            }
            int cnt = deg - j0; if (cnt > 32) cnt = 32;
            for (int t = 0; t < cnt; t++) {
                int   nn = __shfl_sync(0xffffffffu, n, t);
                float pp = __shfl_sync(0xffffffffu, p, t);
                size_t roff = (size_t)nn * D_;
                float4 vt = ((const float4*)&g_xt[roff])[lane];
                float4 vy = ((const float4*)&g_x4[roff])[lane];
                fma4(at, pp, vt);
                fma4(ay, pp, vy);
            }
        }
    }
    if (lane == 0) atomicAdd(&g_alpha, u * u);

    float4 cx = ((const float4*)g_cxt)[lane];
    float4 eo = make_float4(fmaf(u, cx.x, at.x), fmaf(u, cx.y, at.y),
                            fmaf(u, cx.z, at.z), fmaf(u, cx.w, at.w));
    ((float4*)&g_Y[(size_t)e * D_])[lane] = ay;
    *((float4*)&se[wid][lane * 4]) = eo;
    __syncthreads();

    // mini-GEMM: edge4[8 x 128] = se[8 x 128] @ W3[128 x 128]
    int d = tid & 127, sub = tid >> 7;
    const float* w3c = W3 + d;
    const float* r0p = &se[sub*4 + 0][0];
    const float* r1p = &se[sub*4 + 1][0];
    const float* r2p = &se[sub*4 + 2][0];
    const float* r3p = &se[sub*4 + 3][0];
    float a0 = 0.f, b0 = 0.f, c0 = 0.f, d0 = 0.f;
#pragma unroll 8
    for (int k = 0; k < D_; k += 4) {
        float4 e0 = *(const float4*)&r0p[k];
        float4 e1 = *(const float4*)&r1p[k];
        float4 e2 = *(const float4*)&r2p[k];
        float4 e3 = *(const float4*)&r3p[k];
        float w0 = w3c[(k+0)*D_], w1 = w3c[(k+1)*D_];
        float w2 = w3c[(k+2)*D_], w3v = w3c[(k+3)*D_];
        a0 = fmaf(e0.x,w0,fmaf(e0.y,w1,fmaf(e0.z,w2,fmaf(e0.w,w3v,a0))));
        b0 = fmaf(e1.x,w0,fmaf(e1.y,w1,fmaf(e1.z,w2,fmaf(e1.w,w3v,b0))));
        c0 = fmaf(e2.x,w0,fmaf(e2.y,w1,fmaf(e2.z,w2,fmaf(e2.w,w3v,c0))));
        d0 = fmaf(e3.x,w0,fmaf(e3.y,w1,fmaf(e3.z,w2,fmaf(e3.w,w3v,d0))));
    }
    int ebase = blockIdx.x * 8 + sub * 4;
    g_edge4[(size_t)(ebase + 0) * D_ + d] = a0;
    g_edge4[(size_t)(ebase + 1) * D_ + d] = b0;
    g_edge4[(size_t)(ebase + 2) * D_ + d] = c0;
    g_edge4[(size_t)(ebase + 3) * D_ + d] = d0;
}

// fused score + node softmax (warp per node); dn<=32 fast path. Tail: t/p1/p2.
#define N2F_BLOCKS (N_NODES / 8)
__global__ void k_node2f() {
    if (blockIdx.x >= N2F_BLOCKS) {
        int tid = threadIdx.x;
        int d = tid & 127, half = tid >> 7;
        int r0 = (blockIdx.x - N2F_BLOCKS) * 256 + half * 128;
        float t = 0.f, p1 = 0.f, p2 = 0.f;
        for (int r = 0; r < 128; r++) {
            int n = r0 + r;
            float x = g_x4[(size_t)n * D_ + d];
            t  = fmaf(g_v[n], x, t);
            p1 = fmaf(g_w[n], x, p1);
            p2 = fmaf(g_r[n], x, p2);
        }
        atomicAdd(&g_t[d], t);
        atomicAdd(&g_p1[d], p1);
        atomicAdd(&g_p2[d], p2);
        return;
    }
    int n = blockIdx.x * 8 + (threadIdx.x >> 5);
    int lane = threadIdx.x & 31;
    int beg = g_rowptr_n[n], end = g_rowptr_n[n + 1];
    int dn = end - beg;
    float g = 1.0f / ((float)N_EDGES + (float)dn * EM1);

    float4 xv = ((const float4*)&g_x4[(size_t)n * D_])[lane];

    if (dn <= 32) {
        int kreg = 0, ereg = 0;
        if (lane < dn) {
            kreg = g_csr_n[beg + lane];
            ereg = g_kept_e[kreg];
        }
        float sreg = 0.f;
        float m = -INFINITY;
        for (int j = 0; j < dn; j += 2) {
            bool has1 = (j + 1 < dn);
            int j1 = has1 ? j + 1 : j;
            int e0 = __shfl_sync(0xffffffffu, ereg, j);
            int e1 = __shfl_sync(0xffffffffu, ereg, j1);
            float4 ev0 = ((const float4*)&g_edge4[(size_t)e0 * D_])[lane];
            float4 ev1 = ((const float4*)&g_edge4[(size_t)e1 * D_])[lane];
            float s0 = xv.x*ev0.x + xv.y*ev0.y + xv.z*ev0.z + xv.w*ev0.w;
            float s1 = xv.x*ev1.x + xv.y*ev1.y + xv.z*ev1.z + xv.w*ev1.w;
#pragma unroll
            for (int o = 16; o; o >>= 1) {
                s0 += __shfl_xor_sync(0xffffffffu, s0, o);
                s1 += __shfl_xor_sync(0xffffffffu, s1, o);
            }
            s0 *= INV_TEMP; s1 *= INV_TEMP;
            if (lane == j) sreg = s0;
            m = fmaxf(m, s0);
            if (has1) {
                if (lane == j1) sreg = s1;
                m = fmaxf(m, s1);
            }
        }
        float ez = (lane < dn) ? expf(sreg - m) : 0.f;
        float z = ez;
#pragma unroll
        for (int o = 16; o; o >>= 1) z += __shfl_xor_sync(0xffffffffu, z, o);
        float invz = (dn > 0) ? (1.0f / z) : 0.f;
        if (lane < dn) g_Qval[kreg] = EM1 * g + ez * invz;
    } else {
        float m = -INFINITY;
        for (int j = 0; j < dn; j++) {
            int k = g_csr_n[beg + j];
            float4 ev = ((const float4*)&g_edge4[(size_t)g_kept_e[k] * D_])[lane];
            float s = xv.x*ev.x + xv.y*ev.y + xv.z*ev.z + xv.w*ev.w;
#pragma unroll
            for (int o = 16; o; o >>= 1) s += __shfl_xor_sync(0xffffffffu, s, o);
            s *= INV_TEMP;
            if (lane == 0) g_score[k] = s;
            m = fmaxf(m, s);
        }
        float z = 0.f;
        for (int j = lane; j < dn; j += 32) z += expf(g_score[g_csr_n[beg + j]] - m);
#pragma unroll
        for (int o = 16; o; o >>= 1) z += __shfl_xor_sync(0xffffffffu, z, o);
        float invz = 1.0f / z;
        for (int j = lane; j < dn; j += 32) {
            int k = g_csr_n[beg + j];
            g_Qval[k] = EM1 * g + expf(g_score[k] - m) * invz;
        }
    }
}

// Y2 — warp per edge
__global__ void __launch_bounds__(256) k_y2() {
    int lane = threadIdx.x & 31, wid = threadIdx.x >> 5;
    int e = blockIdx.x * 8 + wid;
    int beg = g_rowptr_e[e], end = g_rowptr_e[e + 1];
    int deg = end - beg;
    float4 a = make_float4(0.f,0.f,0.f,0.f);
    for (int j0 = 0; j0 < deg; j0 += 32) {
        int jj = j0 + lane;
        int n = 0; float q = 0.f;
        if (jj < deg) {
            int k = g_csr_e[beg + jj];
            n = g_kept_n[k];
            q = g_Qval[k];
        }
        int cnt = deg - j0; if (cnt > 32) cnt = 32;
        for (int t = 0; t < cnt; t++) {
            int   nn = __shfl_sync(0xffffffffu, n, t);
            float qq = __shfl_sync(0xffffffffu, q, t);
            float4 v = ((const float4*)&g_x4[(size_t)nn * D_])[lane];
            fma4(a, qq, v);
        }
    }
    ((float4*)&g_Y2[(size_t)e * D_])[lane] = a;
}

// final — warp per node
__global__ void __launch_bounds__(256) k_final(float* __restrict__ out) {
    int lane = threadIdx.x & 31, wid = threadIdx.x >> 5;
    int n = blockIdx.x * 8 + wid;
    int beg = g_rowptr_n[n], end = g_rowptr_n[n + 1];
    int dn = end - beg;
    float4 a1 = make_float4(0.f,0.f,0.f,0.f);
    float4 a2 = make_float4(0.f,0.f,0.f,0.f);
    for (int j0 = 0; j0 < dn; j0 += 32) {
        int jj = j0 + lane;
        int e = 0; float p = 0.f, q = 0.f;
        if (jj < dn) {
            int k = g_csr_n[beg + jj];
            e = g_kept_e[k];
            p = g_Pval[k];
            q = g_Qval[k];
        }
        int cnt = dn - j0; if (cnt > 32) cnt = 32;
        for (int t = 0; t < cnt; t++) {
            int   ee = __shfl_sync(0xffffffffu, e, t);
            float pp = __shfl_sync(0xffffffffu, p, t);
            float qq = __shfl_sync(0xffffffffu, q, t);
            size_t roff = (size_t)ee * D_;
            float4 v1 = ((const float4*)&g_Y [roff])[lane];
            float4 v2 = ((const float4*)&g_Y2[roff])[lane];
            fma4(a1, pp, v1);
            fma4(a2, qq, v2);
        }
    }
    float av = g_alpha + g_v[n];
    float wn = g_w[n];
    float cw = (float)N_EDGES * wn + g_r[n];
    float4 sv = ((const float4*)g_s )[lane];
    float4 tv = ((const float4*)g_t )[lane];
    float4 pv = ((const float4*)g_p1)[lane];
    float4 qv = ((const float4*)g_p2)[lane];
    float4 r;
    r.x = av*sv.x + tv.x + cw*pv.x + wn*qv.x + a1.x + a2.x;
    r.y = av*sv.y + tv.y + cw*pv.y + wn*qv.y + a1.y + a2.y;
    r.z = av*sv.z + tv.z + cw*pv.z + wn*qv.z + a1.z + a2.z;
    r.w = av*sv.w + tv.w + cw*pv.w + wn*qv.w + a1.w + a2.w;
    r.x = (r.x > 0.f) ? r.x : expm1f(r.x);
    r.y = (r.y > 0.f) ? r.y : expm1f(r.y);
    r.z = (r.z > 0.f) ? r.z : expm1f(r.z);
    r.w = (r.w > 0.f) ? r.w : expm1f(r.w);
    ((float4*)&out[(size_t)n * D_])[lane] = r;
}

// ---------------- launch ----------------
extern "C" void kernel_launch(void* const* d_in, const int* in_sizes, int n_in,
                              void* d_out, int out_size) {
    const float* x      = (const float*)d_in[0];
    const float* W      = (const float*)d_in[1];
    const float* W2     = (const float*)d_in[2];
    const float* W3     = (const float*)d_in[3];
    const float* bias   = (const float*)d_in[4];
    const float* q_ctx  = (const float*)d_in[5];
    const int*   hidx   = (const int*)d_in[6];
    const int* nodes = hidx;
    const int* edges = hidx + NNZ_IN;
    float* out = (float*)d_out;

    static cudaStream_t s_side = nullptr;
    static cudaEvent_t  ev_fork = nullptr, ev_join = nullptr;
    if (s_side == nullptr) {
        cudaStreamCreateWithFlags(&s_side, cudaStreamNonBlocking);
        cudaEventCreateWithFlags(&ev_fork, cudaEventDisableTiming);
        cudaEventCreateWithFlags(&ev_join, cudaEventDisableTiming);
    }

    k_zero_small<<<1, 256>>>();                              // #1 (main)

    cudaEventRecord(ev_fork, 0);
    cudaStreamWaitEvent(s_side, ev_fork, 0);

    k_zero_big<<<1024, 256, 0, s_side>>>();                  // #2 (side)
    k_dedup<<<NNZ_IN / 256, 256, 0, s_side>>>(nodes, edges); // #3 (side)

    k_gemm_x<<<N_NODES / 32, 256>>>(x, W, W2, bias, q_ctx);  // #4 (main) — profiled

    k_scan2<<<2, 1024, 0, s_side>>>();                       // (side)
    k_fill<<<2 * NNZ_IN / 256, 256, 0, s_side>>>();          // (side)
    cudaEventRecord(ev_join, s_side);

    cudaStreamWaitEvent(0, ev_join, 0);

    k_edge<<<N_EDGES / 8, 256>>>(W3);
    k_node2f<<<N2F_BLOCKS + N_NODES / 256, 256>>>();
    k_y2<<<N_EDGES / 8, 256>>>();
    k_final<<<N_NODES / 8, 256>>>(out);
}

// round 14
// speedup vs baseline: 1.1804x; 1.1804x over previous
#include <cuda_runtime.h>
#include <math.h>

#define N_NODES 8192
#define N_EDGES 4096
#define NNZ_IN  65536
#define DIN_    256
#define D_      128

#define EM1     1.7182818284590452f
#define INV_TEMP (1.0f/11.313708498984761f)  // 1/sqrt(128)

typedef unsigned long long ull;

// ---------------- scratch ----------------
__device__ unsigned int g_bitmap[(size_t)N_NODES * N_EDGES / 32];  // 4 MB
__device__ int   g_kept_n[NNZ_IN];
__device__ int   g_kept_e[NNZ_IN];
__device__ int   g_kept_count;
__device__ int   g_deg_e[N_EDGES];
__device__ int   g_deg_n[N_NODES];
__device__ int   g_rowptr_e[N_EDGES + 1];
__device__ int   g_rowptr_n[N_NODES + 1];
__device__ int   g_cur_e[N_EDGES];
__device__ int   g_cur_n[N_NODES];
__device__ int   g_csr_e[NNZ_IN];   // kept-index, grouped by edge
__device__ int   g_csr_en[NNZ_IN];  // node id, grouped by edge (direct)
__device__ int   g_csr_n[NNZ_IN];   // kept-index, grouped by node
__device__ int   g_csr_ne[NNZ_IN];  // edge id, grouped by node (direct)
__device__ float g_x4[(size_t)N_NODES * D_];
__device__ float g_xt[(size_t)N_NODES * D_];
__device__ float g_rowv[N_NODES];
__device__ float g_edge4[(size_t)N_EDGES * D_];
__device__ float g_Y[(size_t)N_EDGES * D_];
__device__ float g_Y2[(size_t)N_EDGES * D_];
__device__ float g_Pval[NNZ_IN];
__device__ float g_Qval[NNZ_IN];
__device__ float g_score[NNZ_IN];
__device__ float g_v[N_NODES];
__device__ float g_w[N_NODES];
__device__ float g_r[N_NODES];
__device__ float g_s[D_], g_cxt[D_], g_t[D_], g_p1[D_], g_p2[D_];
__device__ float g_alpha;

// ---------------- helpers ----------------
__device__ __forceinline__ void ffma2(ull &acc, ull a, ull b) {
    asm("fma.rn.f32x2 %0, %1, %2, %0;" : "+l"(acc) : "l"(a), "l"(b));
}
__device__ __forceinline__ ull pack2(float v) {
    ull r;
    asm("mov.b64 %0, {%1, %1};" : "=l"(r) : "f"(v));
    return r;
}
__device__ __forceinline__ void unpack2(ull a, float &lo, float &hi) {
    asm("mov.b64 {%0, %1}, %2;" : "=f"(lo), "=f"(hi) : "l"(a));
}
__device__ __forceinline__ void fma4(float4 &a, float p, const float4 &v) {
    a.x = fmaf(p, v.x, a.x); a.y = fmaf(p, v.y, a.y);
    a.z = fmaf(p, v.z, a.z); a.w = fmaf(p, v.w, a.w);
}

// ---------------- kernels ----------------

__global__ void k_zero_small() {
    int i = threadIdx.x;
    if (i < D_) { g_s[i]=0.f; g_cxt[i]=0.f; g_t[i]=0.f; g_p1[i]=0.f; g_p2[i]=0.f; }
    if (i == 0) g_alpha = 0.f;
}

__global__ void k_zero_big() {
    int i = blockIdx.x * blockDim.x + threadIdx.x;
    int stride = gridDim.x * blockDim.x;
    uint4 z4 = make_uint4(0,0,0,0);
    uint4* bm = (uint4*)g_bitmap;
    for (int j = i; j < (int)(sizeof(g_bitmap)/16); j += stride) bm[j] = z4;
    for (int j = i; j < N_EDGES; j += stride) { g_deg_e[j] = 0; g_cur_e[j] = 0; }
    for (int j = i; j < N_NODES; j += stride) { g_deg_n[j] = 0; g_cur_n[j] = 0; g_v[j] = 0.f; }
    if (i == 0) g_kept_count = 0;
}

__global__ void k_dedup(const int* __restrict__ nodes, const int* __restrict__ edges) {
    int i = blockIdx.x * blockDim.x + threadIdx.x;
    if (i >= NNZ_IN) return;
    int n = __ldg(&nodes[i]), e = __ldg(&edges[i]);
    size_t bit = (size_t)e * N_NODES + (size_t)n;
    unsigned int mask = 1u << (bit & 31);
    unsigned int old = atomicOr(&g_bitmap[bit >> 5], mask);
    if (!(old & mask)) {
        int k = atomicAdd(&g_kept_count, 1);
        g_kept_n[k] = n; g_kept_e[k] = e;
        atomicAdd(&g_deg_e[e], 1);
        atomicAdd(&g_deg_n[n], 1);
    }
}

// scans; node pass also emits w,r
__global__ void k_scan2() {
    int which = blockIdx.x;
    const int* cnt = which ? g_deg_n : g_deg_e;
    int* rp        = which ? g_rowptr_n : g_rowptr_e;
    int L          = which ? N_NODES : N_EDGES;
    int tid = threadIdx.x, lane = tid & 31, wid = tid >> 5;
    int C = L >> 10;
    int base = tid * C;
    int loc[8];
    int s = 0;
    for (int j = 0; j < C; j++) { loc[j] = cnt[base + j]; s += loc[j]; }
    int ss = s;
#pragma unroll
    for (int o = 1; o < 32; o <<= 1) { int v = __shfl_up_sync(0xffffffffu, ss, o); if (lane >= o) ss += v; }
    __shared__ int wsum[32];
    if (lane == 31) wsum[wid] = ss;
    __syncthreads();
    if (wid == 0) {
        int v = wsum[lane];
#pragma unroll
        for (int o = 1; o < 32; o <<= 1) { int u = __shfl_up_sync(0xffffffffu, v, o); if (lane >= o) v += u; }
        wsum[lane] = v;
    }
    __syncthreads();
    int run = ss - s + (wid ? wsum[wid - 1] : 0);
    for (int j = 0; j < C; j++) { rp[base + j] = run; run += loc[j]; }
    if (tid == 1023) rp[L] = run;
    if (which) {
        for (int j = 0; j < C; j++) {
            int dn = loc[j];
            float g = 1.0f / ((float)N_EDGES + (float)dn * EM1);
            g_w[base + j] = g + (dn == 0 ? (1.0f / N_EDGES) : 0.0f);
            g_r[base + j] = (dn > 0) ? ((float)dn * EM1 * g + 1.0f) : 0.0f;
        }
    }
}

// fill CSR; also write direct node-id / edge-id arrays (shorter chase later)
__global__ void k_fill() {
    int i = blockIdx.x * blockDim.x + threadIdx.x;
    int kc = g_kept_count;
    if (i < NNZ_IN) {
        if (i >= kc) return;
        int e = g_kept_e[i];
        int n = g_kept_n[i];
        int pe = g_rowptr_e[e] + atomicAdd(&g_cur_e[e], 1);
        g_csr_e[pe]  = i;
        g_csr_en[pe] = n;
    } else {
        i -= NNZ_IN;
        if (i >= kc) return;
        int n = g_kept_n[i];
        int e = g_kept_e[i];
        int pn = g_rowptr_n[n] + atomicAdd(&g_cur_n[n], 1);
        g_csr_n[pn]  = i;
        g_csr_ne[pn] = e;
    }
}

// x4 = x@W2 ; xt = x@W + b ; fused rowv + colsums. (round-11 proven — frozen)
__global__ void __launch_bounds__(512, 2) k_gemm_x(const float* __restrict__ x,
                                                   const float* __restrict__ W,
                                                   const float* __restrict__ W2,
                                                   const float* __restrict__ bias,
                                                   const float* __restrict__ q_ctx) {
    const int ROWS = 32, KC = 32, HR = 8, STRIDE = 36;
    __shared__ __align__(16) float xs[2][KC * STRIDE];
    __shared__ float rvs[ROWS];
    int tid = threadIdx.x;
    int d   = tid & 127;
    int grp = tid >> 7;
    int r0  = blockIdx.x * ROWS;
    int rbase = grp * HR;
    ull a1[4], a2[4];
#pragma unroll
    for (int i = 0; i < 4; i++) { a1[i] = 0ull; a2[i] = 0ull; }

#pragma unroll
    for (int t = tid; t < ROWS * KC; t += 512) {
        int rr = t >> 5, cc = t & 31;
        xs[0][cc * STRIDE + rr] = x[(size_t)(r0 + rr) * DIN_ + cc];
    }
    __syncthreads();

    const int NT = DIN_ / KC;  // 8
    for (int kt = 0; kt < NT; kt++) {
        int cur = kt & 1;
        float pf[2];
        if (kt + 1 < NT) {
            int k0n = (kt + 1) * KC;
#pragma unroll
            for (int t = 0; t < 2; t++) {
                int idx = tid + t * 512;
                int rr = idx >> 5, cc = idx & 31;
                pf[t] = x[(size_t)(r0 + rr) * DIN_ + k0n + cc];
            }
        }
        int k0 = kt * KC;
#pragma unroll
        for (int kk = 0; kk < KC; kk++) {
            ull wp  = pack2(W [(size_t)(k0 + kk) * D_ + d]);
            ull w2p = pack2(W2[(size_t)(k0 + kk) * D_ + d]);
            const ulonglong2* xp = (const ulonglong2*)&xs[cur][kk * STRIDE + rbase];
            ulonglong2 xv0 = xp[0];
            ulonglong2 xv1 = xp[1];
            ffma2(a1[0], xv0.x, wp);  ffma2(a1[1], xv0.y, wp);
            ffma2(a1[2], xv1.x, wp);  ffma2(a1[3], xv1.y, wp);
            ffma2(a2[0], xv0.x, w2p); ffma2(a2[1], xv0.y, w2p);
            ffma2(a2[2], xv1.x, w2p); ffma2(a2[3], xv1.y, w2p);
        }
        if (kt + 1 < NT) {
            __syncthreads();
#pragma unroll
            for (int t = 0; t < 2; t++) {
                int idx = tid + t * 512;
                int rr = idx >> 5, cc = idx & 31;
                xs[cur ^ 1][cc * STRIDE + rr] = pf[t];
            }
            __syncthreads();
        }
    }

    if (tid < ROWS) rvs[tid] = 0.f;
    __syncthreads();

    float b = bias[d], q = q_ctx[d];
    float c4 = 0.f, ct = 0.f;
    int lane = tid & 31;
#pragma unroll
    for (int r = 0; r < 4; r++) {
        int row = r0 + rbase + 2*r;
        float t0, t1, f0, f1;
        unpack2(a1[r], t0, t1);
        unpack2(a2[r], f0, f1);
        t0 += b; t1 += b;
        g_xt[(size_t)(row    ) * D_ + d] = t0;
        g_xt[(size_t)(row + 1) * D_ + d] = t1;
        g_x4[(size_t)(row    ) * D_ + d] = f0;
        g_x4[(size_t)(row + 1) * D_ + d] = f1;
        ct += t0 + t1;
        c4 += f0 + f1;
        float p0 = f0 * q, p1 = f1 * q;
#pragma unroll
        for (int o = 16; o; o >>= 1) {
            p0 += __shfl_xor_sync(0xffffffffu, p0, o);
            p1 += __shfl_xor_sync(0xffffffffu, p1, o);
        }
        if (lane == 0) {
            atomicAdd(&rvs[rbase + 2*r],     p0);
            atomicAdd(&rvs[rbase + 2*r + 1], p1);
        }
    }
    atomicAdd(&g_s[d],   c4);
    atomicAdd(&g_cxt[d], ct);
    __syncthreads();
    if (tid < ROWS) g_rowv[r0 + tid] = rvs[tid] * INV_TEMP;
}

// per edge (warp per edge) + fused edge4 = edge @ W3. Direct node ids.
__global__ void __launch_bounds__(256) k_edge(const float* __restrict__ W3) {
    __shared__ __align__(16) float se[8][132];
    int tid = threadIdx.x, lane = tid & 31, wid = tid >> 5;
    int e = blockIdx.x * 8 + wid;
    int beg = g_rowptr_e[e], end = g_rowptr_e[e + 1];
    int deg = end - beg;
    float c = 1.0f / ((float)N_NODES + (float)deg * EM1);
    float u = c + (deg == 0 ? (1.0f / N_NODES) : 0.0f);

    float4 at = make_float4(0.f,0.f,0.f,0.f);
    float4 ay = make_float4(0.f,0.f,0.f,0.f);

    if (deg <= 32) {
        int k = 0, n = 0; float rv = -INFINITY;
        if (lane < deg) {
            k = g_csr_e[beg + lane];     // independent of n chain
            n = g_csr_en[beg + lane];    // direct node id
            rv = g_rowv[n];
        }
        float m = rv;
#pragma unroll
        for (int o = 16; o; o >>= 1) m = fmaxf(m, __shfl_xor_sync(0xffffffffu, m, o));
        float ez = (lane < deg) ? expf(rv - m) : 0.f;
        float z = ez;
#pragma unroll
        for (int o = 16; o; o >>= 1) z += __shfl_xor_sync(0xffffffffu, z, o);
        float invz = (deg > 0) ? (1.0f / z) : 0.f;
        float p = EM1 * c + ez * invz;
        if (lane < deg) {
            g_Pval[k] = p;
            atomicAdd(&g_v[n], u * p);
        }
        for (int t = 0; t < deg; t++) {
            int   nn = __shfl_sync(0xffffffffu, n, t);
            float pp = __shfl_sync(0xffffffffu, p, t);
            size_t roff = (size_t)nn * D_;
            float4 vt = ((const float4*)&g_xt[roff])[lane];
            float4 vy = ((const float4*)&g_x4[roff])[lane];
            fma4(at, pp, vt);
            fma4(ay, pp, vy);
        }
    } else {
        float m = -INFINITY;
        for (int j = lane; j < deg; j += 32)
            m = fmaxf(m, g_rowv[g_csr_en[beg + j]]);
#pragma unroll
        for (int o = 16; o; o >>= 1) m = fmaxf(m, __shfl_xor_sync(0xffffffffu, m, o));
        float z = 0.f;
        for (int j = lane; j < deg; j += 32)
            z += expf(g_rowv[g_csr_en[beg + j]] - m);
#pragma unroll
        for (int o = 16; o; o >>= 1) z += __shfl_xor_sync(0xffffffffu, z, o);
        float invz = 1.0f / z;
        for (int j0 = 0; j0 < deg; j0 += 32) {
            int jj = j0 + lane;
            int n = 0; float p = 0.f;
            if (jj < deg) {
                int k = g_csr_e[beg + jj];
                n = g_csr_en[beg + jj];
                p = EM1 * c + expf(g_rowv[n] - m) * invz;
                g_Pval[k] = p;
                atomicAdd(&g_v[n], u * p);
            }
            int cnt = deg - j0; if (cnt > 32) cnt = 32;
            for (int t = 0; t < cnt; t++) {
                int   nn = __shfl_sync(0xffffffffu, n, t);
                float pp = __shfl_sync(0xffffffffu, p, t);
                size_t roff = (size_t)nn * D_;
                float4 vt = ((const float4*)&g_xt[roff])[lane];
                float4 vy = ((const float4*)&g_x4[roff])[lane];
                fma4(at, pp, vt);
                fma4(ay, pp, vy);
            }
        }
    }
    if (lane == 0) atomicAdd(&g_alpha, u * u);

    float4 cx = ((const float4*)g_cxt)[lane];
    float4 eo = make_float4(fmaf(u, cx.x, at.x), fmaf(u, cx.y, at.y),
                            fmaf(u, cx.z, at.z), fmaf(u, cx.w, at.w));
    ((float4*)&g_Y[(size_t)e * D_])[lane] = ay;
    *((float4*)&se[wid][lane * 4]) = eo;
    __syncthreads();

    // mini-GEMM: edge4[8 x 128] = se[8 x 128] @ W3[128 x 128]
    int d = tid & 127, sub = tid >> 7;
    const float* w3c = W3 + d;
    const float* r0p = &se[sub*4 + 0][0];
    const float* r1p = &se[sub*4 + 1][0];
    const float* r2p = &se[sub*4 + 2][0];
    const float* r3p = &se[sub*4 + 3][0];
    float a0 = 0.f, b0 = 0.f, c0 = 0.f, d0 = 0.f;
#pragma unroll 8
    for (int k = 0; k < D_; k += 4) {
        float4 e0 = *(const float4*)&r0p[k];
        float4 e1 = *(const float4*)&r1p[k];
        float4 e2 = *(const float4*)&r2p[k];
        float4 e3 = *(const float4*)&r3p[k];
        float w0 = w3c[(k+0)*D_], w1 = w3c[(k+1)*D_];
        float w2 = w3c[(k+2)*D_], w3v = w3c[(k+3)*D_];
        a0 = fmaf(e0.x,w0,fmaf(e0.y,w1,fmaf(e0.z,w2,fmaf(e0.w,w3v,a0))));
        b0 = fmaf(e1.x,w0,fmaf(e1.y,w1,fmaf(e1.z,w2,fmaf(e1.w,w3v,b0))));
        c0 = fmaf(e2.x,w0,fmaf(e2.y,w1,fmaf(e2.z,w2,fmaf(e2.w,w3v,c0))));
        d0 = fmaf(e3.x,w0,fmaf(e3.y,w1,fmaf(e3.z,w2,fmaf(e3.w,w3v,d0))));
    }
    int ebase = blockIdx.x * 8 + sub * 4;
    g_edge4[(size_t)(ebase + 0) * D_ + d] = a0;
    g_edge4[(size_t)(ebase + 1) * D_ + d] = b0;
    g_edge4[(size_t)(ebase + 2) * D_ + d] = c0;
    g_edge4[(size_t)(ebase + 3) * D_ + d] = d0;
}

// fused score + node softmax (warp per node); dn<=32 fast path. Tail: t/p1/p2.
#define N2F_BLOCKS (N_NODES / 8)
__global__ void k_node2f() {
    if (blockIdx.x >= N2F_BLOCKS) {
        int tid = threadIdx.x;
        int d = tid & 127, half = tid >> 7;
        int r0 = (blockIdx.x - N2F_BLOCKS) * 256 + half * 128;
        float t = 0.f, p1 = 0.f, p2 = 0.f;
        for (int r = 0; r < 128; r++) {
            int n = r0 + r;
            float x = g_x4[(size_t)n * D_ + d];
            t  = fmaf(g_v[n], x, t);
            p1 = fmaf(g_w[n], x, p1);
            p2 = fmaf(g_r[n], x, p2);
        }
        atomicAdd(&g_t[d], t);
        atomicAdd(&g_p1[d], p1);
        atomicAdd(&g_p2[d], p2);
        return;
    }
    int n = blockIdx.x * 8 + (threadIdx.x >> 5);
    int lane = threadIdx.x & 31;
    int beg = g_rowptr_n[n], end = g_rowptr_n[n + 1];
    int dn = end - beg;
    float g = 1.0f / ((float)N_EDGES + (float)dn * EM1);

    float4 xv = ((const float4*)&g_x4[(size_t)n * D_])[lane];

    if (dn <= 32) {
        int kreg = 0, ereg = 0;
        if (lane < dn) {
            kreg = g_csr_n[beg + lane];
            ereg = g_csr_ne[beg + lane];   // direct edge id, independent load
        }
        float sreg = 0.f;
        float m = -INFINITY;
        for (int j = 0; j < dn; j += 2) {
            bool has1 = (j + 1 < dn);
            int j1 = has1 ? j + 1 : j;
            int e0 = __shfl_sync(0xffffffffu, ereg, j);
            int e1 = __shfl_sync(0xffffffffu, ereg, j1);
            float4 ev0 = ((const float4*)&g_edge4[(size_t)e0 * D_])[lane];
            float4 ev1 = ((const float4*)&g_edge4[(size_t)e1 * D_])[lane];
            float s0 = xv.x*ev0.x + xv.y*ev0.y + xv.z*ev0.z + xv.w*ev0.w;
            float s1 = xv.x*ev1.x + xv.y*ev1.y + xv.z*ev1.z + xv.w*ev1.w;
#pragma unroll
            for (int o = 16; o; o >>= 1) {
                s0 += __shfl_xor_sync(0xffffffffu, s0, o);
                s1 += __shfl_xor_sync(0xffffffffu, s1, o);
            }
            s0 *= INV_TEMP; s1 *= INV_TEMP;
            if (lane == j) sreg = s0;
            m = fmaxf(m, s0);
            if (has1) {
                if (lane == j1) sreg = s1;
                m = fmaxf(m, s1);
            }
        }
        float ez = (lane < dn) ? expf(sreg - m) : 0.f;
        float z = ez;
#pragma unroll
        for (int o = 16; o; o >>= 1) z += __shfl_xor_sync(0xffffffffu, z, o);
        float invz = (dn > 0) ? (1.0f / z) : 0.f;
        if (lane < dn) g_Qval[kreg] = EM1 * g + ez * invz;
    } else {
        float m = -INFINITY;
        for (int j = 0; j < dn; j++) {
            int k = g_csr_n[beg + j];
            float4 ev = ((const float4*)&g_edge4[(size_t)g_csr_ne[beg + j] * D_])[lane];
            float s = xv.x*ev.x + xv.y*ev.y + xv.z*ev.z + xv.w*ev.w;
#pragma unroll
            for (int o = 16; o; o >>= 1) s += __shfl_xor_sync(0xffffffffu, s, o);
            s *= INV_TEMP;
            if (lane == 0) g_score[k] = s;
            m = fmaxf(m, s);
        }
        float z = 0.f;
        for (int j = lane; j < dn; j += 32) z += expf(g_score[g_csr_n[beg + j]] - m);
#pragma unroll
        for (int o = 16; o; o >>= 1) z += __shfl_xor_sync(0xffffffffu, z, o);
        float invz = 1.0f / z;
        for (int j = lane; j < dn; j += 32) {
            int k = g_csr_n[beg + j];
            g_Qval[k] = EM1 * g + expf(g_score[k] - m) * invz;
        }
    }
}

// Y2 — warp per edge, direct node ids
__global__ void __launch_bounds__(256) k_y2() {
    int lane = threadIdx.x & 31, wid = threadIdx.x >> 5;
    int e = blockIdx.x * 8 + wid;
    int beg = g_rowptr_e[e], end = g_rowptr_e[e + 1];
    int deg = end - beg;
    float4 a = make_float4(0.f,0.f,0.f,0.f);
    for (int j0 = 0; j0 < deg; j0 += 32) {
        int jj = j0 + lane;
        int n = 0; float q = 0.f;
        if (jj < deg) {
            n = g_csr_en[beg + jj];            // direct
            q = g_Qval[g_csr_e[beg + jj]];     // independent root
        }
        int cnt = deg - j0; if (cnt > 32) cnt = 32;
        for (int t = 0; t < cnt; t++) {
            int   nn = __shfl_sync(0xffffffffu, n, t);
            float qq = __shfl_sync(0xffffffffu, q, t);
            float4 v = ((const float4*)&g_x4[(size_t)nn * D_])[lane];
            fma4(a, qq, v);
        }
    }
    ((float4*)&g_Y2[(size_t)e * D_])[lane] = a;
}

// final — warp per node, direct edge ids
__global__ void __launch_bounds__(256) k_final(float* __restrict__ out) {
    int lane = threadIdx.x & 31, wid = threadIdx.x >> 5;
    int n = blockIdx.x * 8 + wid;
    int beg = g_rowptr_n[n], end = g_rowptr_n[n + 1];
    int dn = end - beg;
    float4 a1 = make_float4(0.f,0.f,0.f,0.f);
    float4 a2 = make_float4(0.f,0.f,0.f,0.f);
    for (int j0 = 0; j0 < dn; j0 += 32) {
        int jj = j0 + lane;
        int e = 0; float p = 0.f, q = 0.f;
        if (jj < dn) {
            int k = g_csr_n[beg + jj];
            e = g_csr_ne[beg + jj];            // direct, independent
            p = g_Pval[k];
            q = g_Qval[k];
        }
        int cnt = dn - j0; if (cnt > 32) cnt = 32;
        for (int t = 0; t < cnt; t++) {
            int   ee = __shfl_sync(0xffffffffu, e, t);
            float pp = __shfl_sync(0xffffffffu, p, t);
            float qq = __shfl_sync(0xffffffffu, q, t);
            size_t roff = (size_t)ee * D_;
            float4 v1 = ((const float4*)&g_Y [roff])[lane];
            float4 v2 = ((const float4*)&g_Y2[roff])[lane];
            fma4(a1, pp, v1);
            fma4(a2, qq, v2);
        }
    }
    float av = g_alpha + g_v[n];
    float wn = g_w[n];
    float cw = (float)N_EDGES * wn + g_r[n];
    float4 sv = ((const float4*)g_s )[lane];
    float4 tv = ((const float4*)g_t )[lane];
    float4 pv = ((const float4*)g_p1)[lane];
    float4 qv = ((const float4*)g_p2)[lane];
    float4 r;
    r.x = av*sv.x + tv.x + cw*pv.x + wn*qv.x + a1.x + a2.x;
    r.y = av*sv.y + tv.y + cw*pv.y + wn*qv.y + a1.y + a2.y;
    r.z = av*sv.z + tv.z + cw*pv.z + wn*qv.z + a1.z + a2.z;
    r.w = av*sv.w + tv.w + cw*pv.w + wn*qv.w + a1.w + a2.w;
    r.x = (r.x > 0.f) ? r.x : expm1f(r.x);
    r.y = (r.y > 0.f) ? r.y : expm1f(r.y);
    r.z = (r.z > 0.f) ? r.z : expm1f(r.z);
    r.w = (r.w > 0.f) ? r.w : expm1f(r.w);
    ((float4*)&out[(size_t)n * D_])[lane] = r;
}

// ---------------- launch ----------------
extern "C" void kernel_launch(void* const* d_in, const int* in_sizes, int n_in,
                              void* d_out, int out_size) {
    const float* x      = (const float*)d_in[0];
    const float* W      = (const float*)d_in[1];
    const float* W2     = (const float*)d_in[2];
    const float* W3     = (const float*)d_in[3];
    const float* bias   = (const float*)d_in[4];
    const float* q_ctx  = (const float*)d_in[5];
    const int*   hidx   = (const int*)d_in[6];
    const int* nodes = hidx;
    const int* edges = hidx + NNZ_IN;
    float* out = (float*)d_out;

    static cudaStream_t s_side = nullptr;
    static cudaEvent_t  ev_fork = nullptr, ev_join = nullptr;
    if (s_side == nullptr) {
        cudaStreamCreateWithFlags(&s_side, cudaStreamNonBlocking);
        cudaEventCreateWithFlags(&ev_fork, cudaEventDisableTiming);
        cudaEventCreateWithFlags(&ev_join, cudaEventDisableTiming);
    }

    k_zero_small<<<1, 256>>>();                              // #1 (main)

    cudaEventRecord(ev_fork, 0);
    cudaStreamWaitEvent(s_side, ev_fork, 0);

    k_zero_big<<<1024, 256, 0, s_side>>>();                  // #2 (side)
    k_dedup<<<NNZ_IN / 256, 256, 0, s_side>>>(nodes, edges); // #3 (side)

    k_gemm_x<<<N_NODES / 32, 512>>>(x, W, W2, bias, q_ctx);  // #4 (main) — profiled

    k_scan2<<<2, 1024, 0, s_side>>>();                       // (side)
    k_fill<<<2 * NNZ_IN / 256, 256, 0, s_side>>>();          // (side)
    cudaEventRecord(ev_join, s_side);

    cudaStreamWaitEvent(0, ev_join, 0);

    k_edge<<<N_EDGES / 8, 256>>>(W3);
    k_node2f<<<N2F_BLOCKS + N_NODES / 256, 256>>>();
    k_y2<<<N_EDGES / 8, 256>>>();
    k_final<<<N_NODES / 8, 256>>>(out);
}